// round 2
// baseline (speedup 1.0000x reference)
#include <cuda_runtime.h>

#define D 512
#define NDRUGS_MAX 4096

// Scratch: Vd = ((z_drug * d) @ W) * d   (8 MB, device global — allocation-free)
__device__ float g_Vd[NDRUGS_MAX * D];

// ---------------------------------------------------------------------------
// Phase 1: Vd[m, j] = d[j] * sum_k (z[m,k] * d[k]) * W[k,j]
// Tiled fp32 GEMM: BM=BN=64, BK=32, 256 threads, 4x4 microtile per thread.
// ---------------------------------------------------------------------------
__global__ __launch_bounds__(256) void dedicom_gemm_kernel(
    const float* __restrict__ z,
    const float* __restrict__ W,
    const float* __restrict__ local_diag,
    const int*   __restrict__ idx_ptr)
{
    const int BM = 64, BN = 64, BK = 32;
    __shared__ float As[BK][BM + 1];   // +1 pad: conflict-free transposed stores
    __shared__ float Bs[BK][BN];
    __shared__ float Ds[D];

    const int tid = threadIdx.x;

    // broadcast diag row (idx read as int32: low word is correct for int32/int64 LE)
    const int sub_idx = idx_ptr[0];
    const float* dptr = local_diag + sub_idx * D;
    for (int i = tid; i < D; i += 256) Ds[i] = dptr[i];
    __syncthreads();

    const int m0 = blockIdx.y * BM;
    const int j0 = blockIdx.x * BN;
    const int ty = tid >> 4;          // 0..15
    const int tx = tid & 15;          // 0..15

    float acc[4][4] = {};

    for (int k0 = 0; k0 < D; k0 += BK) {
        // Load A tile (64 x 32), scale by d[k], store transposed As[k][m]
        #pragma unroll
        for (int t = 0; t < 2; t++) {
            int i4 = tid + t * 256;          // 0..511 float4 slots
            int m  = i4 >> 3;                // 8 float4 per row
            int k4 = (i4 & 7) * 4;
            float4 v = *(const float4*)(z + (long)(m0 + m) * D + k0 + k4);
            v.x *= Ds[k0 + k4 + 0];
            v.y *= Ds[k0 + k4 + 1];
            v.z *= Ds[k0 + k4 + 2];
            v.w *= Ds[k0 + k4 + 3];
            As[k4 + 0][m] = v.x;
            As[k4 + 1][m] = v.y;
            As[k4 + 2][m] = v.z;
            As[k4 + 3][m] = v.w;
        }
        // Load B tile (32 x 64) straight
        #pragma unroll
        for (int t = 0; t < 2; t++) {
            int i4 = tid + t * 256;
            int k  = i4 >> 4;                // 16 float4 per row
            int j4 = (i4 & 15) * 4;
            *(float4*)&Bs[k][j4] = *(const float4*)(W + (long)(k0 + k) * D + j0 + j4);
        }
        __syncthreads();

        #pragma unroll
        for (int kk = 0; kk < BK; kk++) {
            float av[4], bv[4];
            #pragma unroll
            for (int i = 0; i < 4; i++) av[i] = As[kk][ty * 4 + i];
            float4 b4 = *(const float4*)&Bs[kk][tx * 4];
            bv[0] = b4.x; bv[1] = b4.y; bv[2] = b4.z; bv[3] = b4.w;
            #pragma unroll
            for (int i = 0; i < 4; i++)
                #pragma unroll
                for (int j = 0; j < 4; j++)
                    acc[i][j] = fmaf(av[i], bv[j], acc[i][j]);
        }
        __syncthreads();
    }

    // Epilogue: scale by d[j], write Vd
    #pragma unroll
    for (int i = 0; i < 4; i++) {
        int m = m0 + ty * 4 + i;
        #pragma unroll
        for (int j = 0; j < 4; j++) {
            int jj = j0 + tx * 4 + j;
            g_Vd[(long)m * D + jj] = acc[i][j] * Ds[jj];
        }
    }
}

// ---------------------------------------------------------------------------
// Phase 2: one warp per edge — score = Vd[r] . z[c], sigmoid, store.
// Edge indices are int32 (JAX x64-disabled downcasts the int64 request).
// ---------------------------------------------------------------------------
__global__ __launch_bounds__(256) void dedicom_edge_kernel(
    const float* __restrict__ z,
    const int* __restrict__ edges,
    float* __restrict__ out,
    int n_edges)
{
    const int w    = (blockIdx.x * blockDim.x + threadIdx.x) >> 5;
    const int lane = threadIdx.x & 31;
    if (w >= n_edges) return;

    const int r = edges[w];
    const int c = edges[n_edges + w];

    const float4* vr = (const float4*)(g_Vd + (long)r * D);
    const float4* zc = (const float4*)(z + (long)c * D);

    float acc = 0.f;
    #pragma unroll
    for (int i = 0; i < 4; i++) {
        float4 a = __ldg(&vr[lane + i * 32]);
        float4 b = __ldg(&zc[lane + i * 32]);
        acc += a.x * b.x + a.y * b.y + a.z * b.z + a.w * b.w;
    }
    #pragma unroll
    for (int o = 16; o; o >>= 1) acc += __shfl_xor_sync(0xffffffffu, acc, o);

    if (lane == 0) out[w] = 1.f / (1.f + expf(-acc));
}

// ---------------------------------------------------------------------------
// Launch
// ---------------------------------------------------------------------------
extern "C" void kernel_launch(void* const* d_in, const int* in_sizes, int n_in,
                              void* d_out, int out_size)
{
    const float* z     = (const float*)d_in[0];   // [n_drugs, 512]
    const float* W     = (const float*)d_in[1];   // [512, 512]
    const float* ldiag = (const float*)d_in[2];   // [10, 512]
    const int*   edges = (const int*)d_in[3];     // [2, n_edges] int32
    const int*   idxp  = (const int*)d_in[4];     // scalar

    const int n_drugs = in_sizes[0] / D;
    const int n_edges = in_sizes[3] / 2;

    dim3 g1(D / 64, n_drugs / 64);
    dedicom_gemm_kernel<<<g1, 256>>>(z, W, ldiag, idxp);

    int blocks = (n_edges + 7) / 8;   // 8 warps / block
    dedicom_edge_kernel<<<blocks, 256>>>(z, edges, (float*)d_out, n_edges);
}

// round 4
// speedup vs baseline: 1.7756x; 1.7756x over previous
#include <cuda_runtime.h>
#include <cuda_bf16.h>
#include <cstdint>

#define D 512
#define NDRUGS 4096
#define BM 128
#define BN 128
#define BK 64

// ---------------- device scratch (allocation-free) ----------------
__device__ __align__(16) float          g_Vd[NDRUGS * D];     // 8 MB
__device__ __align__(16) __nv_bfloat16  g_Ah[NDRUGS * D];     // 4 MB
__device__ __align__(16) __nv_bfloat16  g_Al[NDRUGS * D];     // 4 MB
__device__ __align__(16) __nv_bfloat16  g_Bh[D * D];          // 512 KB (W^T hi)
__device__ __align__(16) __nv_bfloat16  g_Bl[D * D];          // 512 KB (W^T lo)

// ---------------- helpers ----------------
__device__ __forceinline__ uint32_t smem_to_u32(const void* p) {
    uint32_t a;
    asm("{ .reg .u64 t; cvta.to.shared.u64 t, %1; cvt.u32.u64 %0, t; }" : "=r"(a) : "l"(p));
    return a;
}
#define SMEM_SWIZZLE_128B(o) ((o) ^ (((o) >> 3) & 0x70))

#define CP_ASYNC16(dst, src) \
    asm volatile("cp.async.cg.shared.global [%0], [%1], 16;" :: "r"(dst), "l"(src))
#define CP_COMMIT() asm volatile("cp.async.commit_group;" ::: "memory")
#define CP_WAIT(n)  asm volatile("cp.async.wait_group %0;" :: "n"(n) : "memory")

__device__ __forceinline__ void ldsm_x4(uint32_t& r0, uint32_t& r1, uint32_t& r2, uint32_t& r3,
                                        uint32_t addr) {
    asm volatile("ldmatrix.sync.aligned.m8n8.x4.shared.b16 {%0,%1,%2,%3}, [%4];"
                 : "=r"(r0), "=r"(r1), "=r"(r2), "=r"(r3) : "r"(addr));
}
__device__ __forceinline__ void mma_bf16(float* c, const uint32_t* a, uint32_t b0, uint32_t b1) {
    asm volatile("mma.sync.aligned.m16n8k16.row.col.f32.bf16.bf16.f32 "
                 "{%0,%1,%2,%3}, {%4,%5,%6,%7}, {%8,%9}, {%0,%1,%2,%3};"
                 : "+f"(c[0]), "+f"(c[1]), "+f"(c[2]), "+f"(c[3])
                 : "r"(a[0]), "r"(a[1]), "r"(a[2]), "r"(a[3]), "r"(b0), "r"(b1));
}

// SMEM: 2 stages x (Ah 16K | Al 16K | Bh 16K | Bl 16K) + diag 2K
#define STAGE_BYTES 65536
#define AH_OFF 0
#define AL_OFF 16384
#define BH_OFF 32768
#define BL_OFF 49152
#define SM_TOTAL (2 * STAGE_BYTES + D * 4)

// ---------------------------------------------------------------------------
// Prep A: Ah/Al = split-bf16 of z[m,k] * d[k]
// ---------------------------------------------------------------------------
__global__ __launch_bounds__(256) void prep_a_kernel(
    const float* __restrict__ z, const float* __restrict__ ldiag, const int* __restrict__ idxp)
{
    const float* dp = ldiag + idxp[0] * D;
    int i = blockIdx.x * 256 + threadIdx.x;     // float4 index over NDRUGS*D/4
    int k4 = (i & (D / 4 - 1)) << 2;
    float4 v = ((const float4*)z)[i];
    v.x *= dp[k4 + 0]; v.y *= dp[k4 + 1]; v.z *= dp[k4 + 2]; v.w *= dp[k4 + 3];

    __nv_bfloat16 hx = __float2bfloat16(v.x), hy = __float2bfloat16(v.y);
    __nv_bfloat16 hz = __float2bfloat16(v.z), hw = __float2bfloat16(v.w);
    __nv_bfloat16 lx = __float2bfloat16(v.x - __bfloat162float(hx));
    __nv_bfloat16 ly = __float2bfloat16(v.y - __bfloat162float(hy));
    __nv_bfloat16 lz = __float2bfloat16(v.z - __bfloat162float(hz));
    __nv_bfloat16 lw = __float2bfloat16(v.w - __bfloat162float(hw));

    __nv_bfloat162 h01{hx, hy}, h23{hz, hw}, l01{lx, ly}, l23{lz, lw};
    uint2 hp, lp;
    hp.x = *(uint32_t*)&h01; hp.y = *(uint32_t*)&h23;
    lp.x = *(uint32_t*)&l01; lp.y = *(uint32_t*)&l23;
    ((uint2*)g_Ah)[i] = hp;
    ((uint2*)g_Al)[i] = lp;
}

// ---------------------------------------------------------------------------
// Prep W: Bt[n,k] = W[k,n], split-bf16
// ---------------------------------------------------------------------------
__global__ __launch_bounds__(256) void prep_w_kernel(const float* __restrict__ W)
{
    __shared__ float t[32][33];
    int tx = threadIdx.x, ty = threadIdx.y;
    int x0 = blockIdx.x * 32, y0 = blockIdx.y * 32;
    #pragma unroll
    for (int r = 0; r < 4; r++)
        t[ty + r * 8][tx] = W[(y0 + ty + r * 8) * D + x0 + tx];
    __syncthreads();
    #pragma unroll
    for (int r = 0; r < 4; r++) {
        int n = x0 + ty + r * 8;
        int k = y0 + tx;
        float v = t[tx][ty + r * 8];
        __nv_bfloat16 h = __float2bfloat16(v);
        __nv_bfloat16 l = __float2bfloat16(v - __bfloat162float(h));
        g_Bh[n * D + k] = h;
        g_Bl[n * D + k] = l;
    }
}

// ---------------------------------------------------------------------------
// Split-bf16 GEMM via mma.sync (HMMA): Vd = ((Z*d) @ W) * d
// grid (D/BN=4, NDRUGS/BM=32), 256 threads, double-buffered cp.async
// ---------------------------------------------------------------------------
__global__ __launch_bounds__(256, 1) void dedicom_mma_kernel(
    const float* __restrict__ ldiag, const int* __restrict__ idxp)
{
    extern __shared__ char smem[];
    float* ds = (float*)(smem + 2 * STAGE_BYTES);

    const int tid  = threadIdx.x;
    const int wid  = tid >> 5;
    const int lane = tid & 31;
    const int m0 = blockIdx.y * BM;
    const int n0 = blockIdx.x * BN;
    const uint32_t sbase = smem_to_u32(smem);

    // diag into smem (visibility guaranteed by pipeline's __syncthreads)
    {
        const float* dp = ldiag + idxp[0] * D;
        for (int i = tid; i < D; i += 256) ds[i] = dp[i];
    }

    // warp tile: 32(m) x 64(n)
    const int wm = (wid & 3) * 32;
    const int wn = (wid >> 2) * 64;

    float acc[2][8][4];
    #pragma unroll
    for (int a = 0; a < 2; a++)
        #pragma unroll
        for (int b = 0; b < 8; b++)
            #pragma unroll
            for (int c = 0; c < 4; c++) acc[a][b][c] = 0.f;

    // ---- stage loader: 4 arrays, [128 rows x 64 bf16] each, SW128 swizzled ----
    auto load_stage = [&](int kc, int stg) {
        const int k0 = kc * BK;
        const uint32_t b = sbase + stg * STAGE_BYTES;
        #pragma unroll
        for (int t = tid; t < 1024; t += 256) {
            int m = t >> 3, j = t & 7;
            uint32_t sw = SMEM_SWIZZLE_128B((uint32_t)(m * 128 + j * 16));
            CP_ASYNC16(b + AH_OFF + sw, (const char*)(g_Ah + (m0 + m) * D + k0) + j * 16);
            CP_ASYNC16(b + AL_OFF + sw, (const char*)(g_Al + (m0 + m) * D + k0) + j * 16);
            CP_ASYNC16(b + BH_OFF + sw, (const char*)(g_Bh + (n0 + m) * D + k0) + j * 16);
            CP_ASYNC16(b + BL_OFF + sw, (const char*)(g_Bl + (n0 + m) * D + k0) + j * 16);
        }
    };

    load_stage(0, 0); CP_COMMIT();

    const int NKC = D / BK;   // 8
    for (int kc = 0; kc < NKC; kc++) {
        if (kc + 1 < NKC) { load_stage(kc + 1, (kc + 1) & 1); CP_COMMIT(); CP_WAIT(1); }
        else              { CP_WAIT(0); }
        __syncthreads();

        const uint32_t sb = sbase + (kc & 1) * STAGE_BYTES;

        #pragma unroll
        for (int ks = 0; ks < BK / 16; ks++) {
            uint32_t ah[2][4], al[2][4], bh[4][4], bl[4][4];

            // A fragments: rows wm+mt*16+(lane&15), k byte ks*32 + (lane>>4)*16
            #pragma unroll
            for (int mt = 0; mt < 2; mt++) {
                uint32_t off = SMEM_SWIZZLE_128B(
                    (uint32_t)((wm + mt * 16 + (lane & 15)) * 128 + ks * 32 + (lane >> 4) * 16));
                ldsm_x4(ah[mt][0], ah[mt][1], ah[mt][2], ah[mt][3], sb + AH_OFF + off);
                ldsm_x4(al[mt][0], al[mt][1], al[mt][2], al[mt][3], sb + AL_OFF + off);
            }
            // B fragments: 4 x (n16 x k16) -> two n8k16 frags each
            #pragma unroll
            for (int p = 0; p < 4; p++) {
                uint32_t off = SMEM_SWIZZLE_128B(
                    (uint32_t)((wn + p * 16 + ((lane >> 4) * 8) + (lane & 7)) * 128
                               + ks * 32 + ((lane >> 3) & 1) * 16));
                ldsm_x4(bh[p][0], bh[p][1], bh[p][2], bh[p][3], sb + BH_OFF + off);
                ldsm_x4(bl[p][0], bl[p][1], bl[p][2], bl[p][3], sb + BL_OFF + off);
            }
            // 3-product accumulation: AhBh + AhBl + AlBh
            #pragma unroll
            for (int mt = 0; mt < 2; mt++) {
                #pragma unroll
                for (int p = 0; p < 4; p++) {
                    mma_bf16(acc[mt][2 * p + 0], ah[mt], bh[p][0], bh[p][1]);
                    mma_bf16(acc[mt][2 * p + 0], ah[mt], bl[p][0], bl[p][1]);
                    mma_bf16(acc[mt][2 * p + 0], al[mt], bh[p][0], bh[p][1]);
                    mma_bf16(acc[mt][2 * p + 1], ah[mt], bh[p][2], bh[p][3]);
                    mma_bf16(acc[mt][2 * p + 1], ah[mt], bl[p][2], bl[p][3]);
                    mma_bf16(acc[mt][2 * p + 1], al[mt], bh[p][2], bh[p][3]);
                }
            }
        }
        __syncthreads();
    }

    // epilogue: scale by d[j], write Vd (float2 per fragment row)
    const int g  = lane >> 2;
    const int c2 = (lane & 3) * 2;
    #pragma unroll
    for (int mt = 0; mt < 2; mt++) {
        const int row0 = m0 + wm + mt * 16 + g;
        #pragma unroll
        for (int nt = 0; nt < 8; nt++) {
            const int col = wn + nt * 8 + c2;        // 0..127 within tile
            const float dx = ds[n0 + col], dy = ds[n0 + col + 1];
            float2 v0 = { acc[mt][nt][0] * dx, acc[mt][nt][1] * dy };
            float2 v1 = { acc[mt][nt][2] * dx, acc[mt][nt][3] * dy };
            *(float2*)(g_Vd + (long)row0 * D + n0 + col)       = v0;
            *(float2*)(g_Vd + (long)(row0 + 8) * D + n0 + col) = v1;
        }
    }
}

// ---------------------------------------------------------------------------
// Phase 2: one warp per edge — score = Vd[r] . z[c], sigmoid, store.
// ---------------------------------------------------------------------------
__global__ __launch_bounds__(256) void dedicom_edge_kernel(
    const float* __restrict__ z,
    const int* __restrict__ edges,
    float* __restrict__ out,
    int n_edges)
{
    const int w    = (blockIdx.x * blockDim.x + threadIdx.x) >> 5;
    const int lane = threadIdx.x & 31;
    if (w >= n_edges) return;

    const int r = edges[w];
    const int c = edges[n_edges + w];

    const float4* vr = (const float4*)(g_Vd + (long)r * D);
    const float4* zc = (const float4*)(z + (long)c * D);

    float acc = 0.f;
    #pragma unroll
    for (int i = 0; i < 4; i++) {
        float4 a = __ldg(&vr[lane + i * 32]);
        float4 b = __ldg(&zc[lane + i * 32]);
        acc += a.x * b.x + a.y * b.y + a.z * b.z + a.w * b.w;
    }
    #pragma unroll
    for (int o = 16; o; o >>= 1) acc += __shfl_xor_sync(0xffffffffu, acc, o);

    if (lane == 0) out[w] = 1.f / (1.f + expf(-acc));
}

// ---------------------------------------------------------------------------
// Launch
// ---------------------------------------------------------------------------
extern "C" void kernel_launch(void* const* d_in, const int* in_sizes, int n_in,
                              void* d_out, int out_size)
{
    const float* z     = (const float*)d_in[0];   // [4096, 512]
    const float* W     = (const float*)d_in[1];   // [512, 512]
    const float* ldiag = (const float*)d_in[2];   // [10, 512]
    const int*   edges = (const int*)d_in[3];     // [2, n_edges] int32
    const int*   idxp  = (const int*)d_in[4];     // scalar

    const int n_drugs = in_sizes[0] / D;
    const int n_edges = in_sizes[3] / 2;

    static int smem_set = 0;
    if (!smem_set) {
        cudaFuncSetAttribute(dedicom_mma_kernel,
                             cudaFuncAttributeMaxDynamicSharedMemorySize, SM_TOTAL);
        smem_set = 1;
    }

    prep_a_kernel<<<(n_drugs * D / 4 + 255) / 256, 256>>>(z, ldiag, idxp);
    prep_w_kernel<<<dim3(D / 32, D / 32), dim3(32, 8)>>>(W);

    dim3 gm(D / BN, n_drugs / BM);
    dedicom_mma_kernel<<<gm, 256, SM_TOTAL>>>(ldiag, idxp);

    int blocks = (n_edges + 7) / 8;
    dedicom_edge_kernel<<<blocks, 256>>>(z, edges, (float*)d_out, n_edges);
}

// round 5
// speedup vs baseline: 2.0908x; 1.1775x over previous
#include <cuda_runtime.h>
#include <cuda_bf16.h>
#include <cstdint>

#define D 512
#define NDRUGS 4096
#define BM 128
#define BN 128
#define BK 64

// ---------------- device scratch (allocation-free) ----------------
__device__ __align__(16) __nv_bfloat16  g_Vdh[NDRUGS * D];    // 4 MB (Vd in bf16)
__device__ __align__(16) __nv_bfloat16  g_Zb[NDRUGS * D];     // 4 MB (raw z in bf16)
__device__ __align__(16) __nv_bfloat16  g_Ah[NDRUGS * D];     // 4 MB
__device__ __align__(16) __nv_bfloat16  g_Al[NDRUGS * D];     // 4 MB
__device__ __align__(16) __nv_bfloat16  g_Bh[D * D];          // 512 KB (W^T hi)
__device__ __align__(16) __nv_bfloat16  g_Bl[D * D];          // 512 KB (W^T lo)

// ---------------- helpers ----------------
__device__ __forceinline__ uint32_t smem_to_u32(const void* p) {
    uint32_t a;
    asm("{ .reg .u64 t; cvta.to.shared.u64 t, %1; cvt.u32.u64 %0, t; }" : "=r"(a) : "l"(p));
    return a;
}
#define SMEM_SWIZZLE_128B(o) ((o) ^ (((o) >> 3) & 0x70))

#define CP_ASYNC16(dst, src) \
    asm volatile("cp.async.cg.shared.global [%0], [%1], 16;" :: "r"(dst), "l"(src))
#define CP_COMMIT() asm volatile("cp.async.commit_group;" ::: "memory")
#define CP_WAIT(n)  asm volatile("cp.async.wait_group %0;" :: "n"(n) : "memory")

__device__ __forceinline__ void ldsm_x4(uint32_t& r0, uint32_t& r1, uint32_t& r2, uint32_t& r3,
                                        uint32_t addr) {
    asm volatile("ldmatrix.sync.aligned.m8n8.x4.shared.b16 {%0,%1,%2,%3}, [%4];"
                 : "=r"(r0), "=r"(r1), "=r"(r2), "=r"(r3) : "r"(addr));
}
__device__ __forceinline__ void mma_bf16(float* c, const uint32_t* a, uint32_t b0, uint32_t b1) {
    asm volatile("mma.sync.aligned.m16n8k16.row.col.f32.bf16.bf16.f32 "
                 "{%0,%1,%2,%3}, {%4,%5,%6,%7}, {%8,%9}, {%0,%1,%2,%3};"
                 : "+f"(c[0]), "+f"(c[1]), "+f"(c[2]), "+f"(c[3])
                 : "r"(a[0]), "r"(a[1]), "r"(a[2]), "r"(a[3]), "r"(b0), "r"(b1));
}

// SMEM: 2 stages x (Ah 16K | Al 16K | Bh 16K | Bl 16K) + diag 2K
#define STAGE_BYTES 65536
#define AH_OFF 0
#define AL_OFF 16384
#define BH_OFF 32768
#define BL_OFF 49152
#define SM_TOTAL (2 * STAGE_BYTES + D * 4)

// ---------------------------------------------------------------------------
// Prep A: Zb = bf16(z);  Ah/Al = split-bf16 of z[m,k] * d[k]
// ---------------------------------------------------------------------------
__global__ __launch_bounds__(256) void prep_a_kernel(
    const float* __restrict__ z, const float* __restrict__ ldiag, const int* __restrict__ idxp)
{
    const float* dp = ldiag + idxp[0] * D;
    int i = blockIdx.x * 256 + threadIdx.x;     // float4 index over NDRUGS*D/4
    int k4 = (i & (D / 4 - 1)) << 2;
    float4 v = ((const float4*)z)[i];

    // raw z in bf16 for the edge phase
    {
        __nv_bfloat162 z01 = __floats2bfloat162_rn(v.x, v.y);
        __nv_bfloat162 z23 = __floats2bfloat162_rn(v.z, v.w);
        uint2 zp; zp.x = *(uint32_t*)&z01; zp.y = *(uint32_t*)&z23;
        ((uint2*)g_Zb)[i] = zp;
    }

    v.x *= dp[k4 + 0]; v.y *= dp[k4 + 1]; v.z *= dp[k4 + 2]; v.w *= dp[k4 + 3];

    __nv_bfloat16 hx = __float2bfloat16(v.x), hy = __float2bfloat16(v.y);
    __nv_bfloat16 hz = __float2bfloat16(v.z), hw = __float2bfloat16(v.w);
    __nv_bfloat16 lx = __float2bfloat16(v.x - __bfloat162float(hx));
    __nv_bfloat16 ly = __float2bfloat16(v.y - __bfloat162float(hy));
    __nv_bfloat16 lz = __float2bfloat16(v.z - __bfloat162float(hz));
    __nv_bfloat16 lw = __float2bfloat16(v.w - __bfloat162float(hw));

    __nv_bfloat162 h01{hx, hy}, h23{hz, hw}, l01{lx, ly}, l23{lz, lw};
    uint2 hp, lp;
    hp.x = *(uint32_t*)&h01; hp.y = *(uint32_t*)&h23;
    lp.x = *(uint32_t*)&l01; lp.y = *(uint32_t*)&l23;
    ((uint2*)g_Ah)[i] = hp;
    ((uint2*)g_Al)[i] = lp;
}

// ---------------------------------------------------------------------------
// Prep W: Bt[n,k] = W[k,n], split-bf16
// ---------------------------------------------------------------------------
__global__ __launch_bounds__(256) void prep_w_kernel(const float* __restrict__ W)
{
    __shared__ float t[32][33];
    int tx = threadIdx.x, ty = threadIdx.y;
    int x0 = blockIdx.x * 32, y0 = blockIdx.y * 32;
    #pragma unroll
    for (int r = 0; r < 4; r++)
        t[ty + r * 8][tx] = W[(y0 + ty + r * 8) * D + x0 + tx];
    __syncthreads();
    #pragma unroll
    for (int r = 0; r < 4; r++) {
        int n = x0 + ty + r * 8;
        int k = y0 + tx;
        float v = t[tx][ty + r * 8];
        __nv_bfloat16 h = __float2bfloat16(v);
        __nv_bfloat16 l = __float2bfloat16(v - __bfloat162float(h));
        g_Bh[n * D + k] = h;
        g_Bl[n * D + k] = l;
    }
}

// ---------------------------------------------------------------------------
// Split-bf16 GEMM via mma.sync (HMMA): Vdh = bf16( ((Z*d) @ W) * d )
// grid (D/BN=4, NDRUGS/BM=32), 256 threads, double-buffered cp.async
// ---------------------------------------------------------------------------
__global__ __launch_bounds__(256, 1) void dedicom_mma_kernel(
    const float* __restrict__ ldiag, const int* __restrict__ idxp)
{
    extern __shared__ char smem[];
    float* ds = (float*)(smem + 2 * STAGE_BYTES);

    const int tid  = threadIdx.x;
    const int wid  = tid >> 5;
    const int lane = tid & 31;
    const int m0 = blockIdx.y * BM;
    const int n0 = blockIdx.x * BN;
    const uint32_t sbase = smem_to_u32(smem);

    {
        const float* dp = ldiag + idxp[0] * D;
        for (int i = tid; i < D; i += 256) ds[i] = dp[i];
    }

    const int wm = (wid & 3) * 32;
    const int wn = (wid >> 2) * 64;

    float acc[2][8][4];
    #pragma unroll
    for (int a = 0; a < 2; a++)
        #pragma unroll
        for (int b = 0; b < 8; b++)
            #pragma unroll
            for (int c = 0; c < 4; c++) acc[a][b][c] = 0.f;

    auto load_stage = [&](int kc, int stg) {
        const int k0 = kc * BK;
        const uint32_t b = sbase + stg * STAGE_BYTES;
        #pragma unroll
        for (int t = tid; t < 1024; t += 256) {
            int m = t >> 3, j = t & 7;
            uint32_t sw = SMEM_SWIZZLE_128B((uint32_t)(m * 128 + j * 16));
            CP_ASYNC16(b + AH_OFF + sw, (const char*)(g_Ah + (m0 + m) * D + k0) + j * 16);
            CP_ASYNC16(b + AL_OFF + sw, (const char*)(g_Al + (m0 + m) * D + k0) + j * 16);
            CP_ASYNC16(b + BH_OFF + sw, (const char*)(g_Bh + (n0 + m) * D + k0) + j * 16);
            CP_ASYNC16(b + BL_OFF + sw, (const char*)(g_Bl + (n0 + m) * D + k0) + j * 16);
        }
    };

    load_stage(0, 0); CP_COMMIT();

    const int NKC = D / BK;   // 8
    for (int kc = 0; kc < NKC; kc++) {
        if (kc + 1 < NKC) { load_stage(kc + 1, (kc + 1) & 1); CP_COMMIT(); CP_WAIT(1); }
        else              { CP_WAIT(0); }
        __syncthreads();

        const uint32_t sb = sbase + (kc & 1) * STAGE_BYTES;

        #pragma unroll
        for (int ks = 0; ks < BK / 16; ks++) {
            uint32_t ah[2][4], al[2][4], bh[4][4], bl[4][4];

            #pragma unroll
            for (int mt = 0; mt < 2; mt++) {
                uint32_t off = SMEM_SWIZZLE_128B(
                    (uint32_t)((wm + mt * 16 + (lane & 15)) * 128 + ks * 32 + (lane >> 4) * 16));
                ldsm_x4(ah[mt][0], ah[mt][1], ah[mt][2], ah[mt][3], sb + AH_OFF + off);
                ldsm_x4(al[mt][0], al[mt][1], al[mt][2], al[mt][3], sb + AL_OFF + off);
            }
            #pragma unroll
            for (int p = 0; p < 4; p++) {
                uint32_t off = SMEM_SWIZZLE_128B(
                    (uint32_t)((wn + p * 16 + ((lane >> 4) * 8) + (lane & 7)) * 128
                               + ks * 32 + ((lane >> 3) & 1) * 16));
                ldsm_x4(bh[p][0], bh[p][1], bh[p][2], bh[p][3], sb + BH_OFF + off);
                ldsm_x4(bl[p][0], bl[p][1], bl[p][2], bl[p][3], sb + BL_OFF + off);
            }
            #pragma unroll
            for (int mt = 0; mt < 2; mt++) {
                #pragma unroll
                for (int p = 0; p < 4; p++) {
                    mma_bf16(acc[mt][2 * p + 0], ah[mt], bh[p][0], bh[p][1]);
                    mma_bf16(acc[mt][2 * p + 0], ah[mt], bl[p][0], bl[p][1]);
                    mma_bf16(acc[mt][2 * p + 0], al[mt], bh[p][0], bh[p][1]);
                    mma_bf16(acc[mt][2 * p + 1], ah[mt], bh[p][2], bh[p][3]);
                    mma_bf16(acc[mt][2 * p + 1], ah[mt], bl[p][2], bl[p][3]);
                    mma_bf16(acc[mt][2 * p + 1], al[mt], bh[p][2], bh[p][3]);
                }
            }
        }
        __syncthreads();
    }

    // epilogue: scale by d[j], write Vdh as bf16 pairs
    const int g  = lane >> 2;
    const int c2 = (lane & 3) * 2;
    #pragma unroll
    for (int mt = 0; mt < 2; mt++) {
        const int row0 = m0 + wm + mt * 16 + g;
        #pragma unroll
        for (int nt = 0; nt < 8; nt++) {
            const int col = wn + nt * 8 + c2;        // 0..127 within tile
            const float dx = ds[n0 + col], dy = ds[n0 + col + 1];
            __nv_bfloat162 v0 = __floats2bfloat162_rn(acc[mt][nt][0] * dx, acc[mt][nt][1] * dy);
            __nv_bfloat162 v1 = __floats2bfloat162_rn(acc[mt][nt][2] * dx, acc[mt][nt][3] * dy);
            *(__nv_bfloat162*)(g_Vdh + (long)row0 * D + n0 + col)       = v0;
            *(__nv_bfloat162*)(g_Vdh + (long)(row0 + 8) * D + n0 + col) = v1;
        }
    }
}

// ---------------------------------------------------------------------------
// Phase 2: one warp per edge — score = Vdh[r] . Zb[c] in bf16, fp32 accumulate.
// Per row: 512 bf16 = 1KB = 2 x LDG.128 per lane stride.
// ---------------------------------------------------------------------------
__global__ __launch_bounds__(256) void dedicom_edge_kernel(
    const int* __restrict__ edges,
    float* __restrict__ out,
    int n_edges)
{
    const int w    = (blockIdx.x * blockDim.x + threadIdx.x) >> 5;
    const int lane = threadIdx.x & 31;
    if (w >= n_edges) return;

    const int r = edges[w];
    const int c = edges[n_edges + w];

    const uint4* vr = (const uint4*)(g_Vdh + (long)r * D);   // 64 uint4 per row
    const uint4* zc = (const uint4*)(g_Zb  + (long)c * D);

    float acc = 0.f;
    #pragma unroll
    for (int i = 0; i < 2; i++) {
        uint4 a = __ldg(&vr[lane + i * 32]);
        uint4 b = __ldg(&zc[lane + i * 32]);
        const uint32_t* ap = &a.x;
        const uint32_t* bp = &b.x;
        #pragma unroll
        for (int j = 0; j < 4; j++) {
            float2 fa = __bfloat1622float2(*(const __nv_bfloat162*)&ap[j]);
            float2 fb = __bfloat1622float2(*(const __nv_bfloat162*)&bp[j]);
            acc = fmaf(fa.x, fb.x, acc);
            acc = fmaf(fa.y, fb.y, acc);
        }
    }
    #pragma unroll
    for (int o = 16; o; o >>= 1) acc += __shfl_xor_sync(0xffffffffu, acc, o);

    if (lane == 0) out[w] = 1.f / (1.f + expf(-acc));
}

// ---------------------------------------------------------------------------
// Launch
// ---------------------------------------------------------------------------
extern "C" void kernel_launch(void* const* d_in, const int* in_sizes, int n_in,
                              void* d_out, int out_size)
{
    const float* z     = (const float*)d_in[0];   // [4096, 512]
    const float* W     = (const float*)d_in[1];   // [512, 512]
    const float* ldiag = (const float*)d_in[2];   // [10, 512]
    const int*   edges = (const int*)d_in[3];     // [2, n_edges] int32
    const int*   idxp  = (const int*)d_in[4];     // scalar

    const int n_drugs = in_sizes[0] / D;
    const int n_edges = in_sizes[3] / 2;

    static int smem_set = 0;
    if (!smem_set) {
        cudaFuncSetAttribute(dedicom_mma_kernel,
                             cudaFuncAttributeMaxDynamicSharedMemorySize, SM_TOTAL);
        smem_set = 1;
    }

    prep_a_kernel<<<(n_drugs * D / 4 + 255) / 256, 256>>>(z, ldiag, idxp);
    prep_w_kernel<<<dim3(D / 32, D / 32), dim3(32, 8)>>>(W);

    dim3 gm(D / BN, n_drugs / BM);
    dedicom_mma_kernel<<<gm, 256, SM_TOTAL>>>(ldiag, idxp);

    int blocks = (n_edges + 7) / 8;
    dedicom_edge_kernel<<<blocks, 256>>>(edges, (float*)d_out, n_edges);
}